// round 6
// baseline (speedup 1.0000x reference)
#include <cuda_runtime.h>
#include <cuda_bf16.h>
#include <math.h>

// TopkRouter: logits = X @ W^T + b ; top-8 ; masked softmax.
// X: [32768, 2048] f32, W: [64, 2048] f32, b: [64] f32
// out: probs [32768, 64] f32 followed by indices [32768, 8] (as f32 values).
//
// Numerics: replicate XLA:CPU / Eigen gebp fp32 accumulation:
// K blocked into panels of kc=320 (Eigen blocking heuristic's 320 cap —
// reached for any l1 >= ~21KB or aarch64 mr=8 traits); serial ascending FMA
// inside a panel; C += panel at each boundary; 128-k remainder panel last;
// bias added once at the end.

#define TOKENS 32768
#define EMBED 2048
#define NEXP 64
#define TOPK 8
#define TPB 128          // tokens per block
#define KT 32            // k tile
#define KC_TILES 10      // flush every 10 tiles => panel = 320 (Eigen cap)
#define XS_STRIDE 36     // 32 + 4 pad, keeps 16B alignment
#define WS_STRIDE 68     // 64 + 4 pad, keeps 16B alignment
#define LG_STRIDE 65     // logits row stride (conflict-free column scans)

static __device__ __forceinline__ unsigned long long pack2(float x) {
    unsigned long long r;
    asm("mov.b64 %0, {%1, %1};" : "=l"(r) : "f"(x));
    return r;
}
static __device__ __forceinline__ unsigned long long ffma2(unsigned long long a,
                                                           unsigned long long b,
                                                           unsigned long long c) {
    unsigned long long d;
    asm("fma.rn.f32x2 %0, %1, %2, %3;" : "=l"(d) : "l"(a), "l"(b), "l"(c));
    return d;
}
static __device__ __forceinline__ unsigned long long fadd2(unsigned long long a,
                                                           unsigned long long b) {
    unsigned long long d;
    asm("add.rn.f32x2 %0, %1, %2;" : "=l"(d) : "l"(a), "l"(b));
    return d;
}
static __device__ __forceinline__ void unpack2(unsigned long long v, float& lo, float& hi) {
    asm("mov.b64 {%0, %1}, %2;" : "=f"(lo), "=f"(hi) : "l"(v));
}

// shared layout (floats):
//   [0, 8320)        union: { Xs[128*36]=4608 | Ws at +4608 (32*68=2176) }  OR logits[128*65]
//   [8320, 9344)     sidx[128*8]
//   [9344, 9408)     sbias[64]
#define SMEM_FLOATS (8320 + 1024 + 64)

__global__ __launch_bounds__(256, 2)
void topk_router_kernel(const float* __restrict__ X,
                        const float* __restrict__ W,
                        const float* __restrict__ B,
                        float* __restrict__ probs_out,
                        float* __restrict__ idx_out) {
    __shared__ float smem[SMEM_FLOATS];
    float* Xs     = smem;               // 128 x 36
    float* Ws     = smem + 4608;        // 32 x 68 (transposed: [k][e])
    float* logits = smem;               // 128 x 65 (overlaps tiles; used after GEMM)
    float* sidx   = smem + 8320;        // 128 x 8
    float* sbias  = smem + 9344;        // 64

    const int tid  = threadIdx.x;
    const int tok0 = blockIdx.x * TPB;

    if (tid < NEXP) sbias[tid] = B[tid];

    const int g = tid >> 3;   // token group: tokens 4g..4g+3
    const int h = tid & 7;    // expert group: experts 8h..8h+7

    // two-level fp32 accumulation: mst += til at every 320-k panel boundary
    unsigned long long mst[4][4];
    unsigned long long til[4][4];
#pragma unroll
    for (int i = 0; i < 4; i++)
#pragma unroll
        for (int j = 0; j < 4; j++) { mst[i][j] = 0ull; til[i][j] = 0ull; }

    for (int k0 = 0; k0 < EMBED; k0 += KT) {
        __syncthreads();
        // ---- load X tile: 128 tokens x 32 k (token-major, float4) ----
#pragma unroll
        for (int r = 0; r < 4; r++) {
            int idx = tid + 256 * r;            // 0..1023
            int t = idx >> 3;
            int c = idx & 7;
            float4 v = *reinterpret_cast<const float4*>(
                X + (size_t)(tok0 + t) * EMBED + k0 + 4 * c);
            *reinterpret_cast<float4*>(Xs + t * XS_STRIDE + 4 * c) = v;
        }
        // ---- load W tile transposed: Ws[k][e] ----
#pragma unroll
        for (int r = 0; r < 2; r++) {
            int idx = tid + 256 * r;            // 0..511
            int e = idx >> 3;
            int c = idx & 7;
            float4 v = *reinterpret_cast<const float4*>(
                W + (size_t)e * EMBED + k0 + 4 * c);
            Ws[(4 * c + 0) * WS_STRIDE + e] = v.x;
            Ws[(4 * c + 1) * WS_STRIDE + e] = v.y;
            Ws[(4 * c + 2) * WS_STRIDE + e] = v.z;
            Ws[(4 * c + 3) * WS_STRIDE + e] = v.w;
        }
        __syncthreads();
        // ---- compute: serial ascending k within the panel ----
#pragma unroll
        for (int kk = 0; kk < KT; kk++) {
            const unsigned long long* wr = reinterpret_cast<const unsigned long long*>(
                Ws + kk * WS_STRIDE + 8 * h);
            unsigned long long w0 = wr[0], w1 = wr[1], w2 = wr[2], w3 = wr[3];
            unsigned long long xx0 = pack2(Xs[(4 * g + 0) * XS_STRIDE + kk]);
            unsigned long long xx1 = pack2(Xs[(4 * g + 1) * XS_STRIDE + kk]);
            unsigned long long xx2 = pack2(Xs[(4 * g + 2) * XS_STRIDE + kk]);
            unsigned long long xx3 = pack2(Xs[(4 * g + 3) * XS_STRIDE + kk]);
            til[0][0] = ffma2(xx0, w0, til[0][0]);
            til[0][1] = ffma2(xx0, w1, til[0][1]);
            til[0][2] = ffma2(xx0, w2, til[0][2]);
            til[0][3] = ffma2(xx0, w3, til[0][3]);
            til[1][0] = ffma2(xx1, w0, til[1][0]);
            til[1][1] = ffma2(xx1, w1, til[1][1]);
            til[1][2] = ffma2(xx1, w2, til[1][2]);
            til[1][3] = ffma2(xx1, w3, til[1][3]);
            til[2][0] = ffma2(xx2, w0, til[2][0]);
            til[2][1] = ffma2(xx2, w1, til[2][1]);
            til[2][2] = ffma2(xx2, w2, til[2][2]);
            til[2][3] = ffma2(xx2, w3, til[2][3]);
            til[3][0] = ffma2(xx3, w0, til[3][0]);
            til[3][1] = ffma2(xx3, w1, til[3][1]);
            til[3][2] = ffma2(xx3, w2, til[3][2]);
            til[3][3] = ffma2(xx3, w3, til[3][3]);
        }
        // ---- Eigen panel boundary: after tiles 9,19,...,59 (k=320,640,...,1920) ----
        {
            int t_idx = k0 >> 5;
            if ((t_idx + 1) % KC_TILES == 0) {
#pragma unroll
                for (int i = 0; i < 4; i++)
#pragma unroll
                    for (int j = 0; j < 4; j++) {
                        mst[i][j] = fadd2(mst[i][j], til[i][j]);
                        til[i][j] = 0ull;
                    }
            }
        }
    }
    // final remainder panel (k = 1920..2047, 128 wide)
#pragma unroll
    for (int i = 0; i < 4; i++)
#pragma unroll
        for (int j = 0; j < 4; j++) mst[i][j] = fadd2(mst[i][j], til[i][j]);

    __syncthreads();   // all warps done reading tiles; safe to overwrite with logits

    // ---- bias add + stash logits in smem ----
#pragma unroll
    for (int i = 0; i < 4; i++) {
        int t = 4 * g + i;
#pragma unroll
        for (int j = 0; j < 4; j++) {
            int e = 8 * h + 2 * j;
            float lo, hi;
            unpack2(mst[i][j], lo, hi);
            logits[t * LG_STRIDE + e]     = lo + sbias[e];
            logits[t * LG_STRIDE + e + 1] = hi + sbias[e + 1];
        }
    }
    __syncthreads();

    // ---- top-8 + masked softmax, one thread per token ----
    if (tid < TPB) {
        float* row = logits + tid * LG_STRIDE;
        float vals[TOPK];
        int   inds[TOPK];
#pragma unroll
        for (int s = 0; s < TOPK; s++) {
            float best = -INFINITY;
            int bi = 0;
            for (int j = 0; j < NEXP; j++) {
                float v = row[j];
                if (v > best) { best = v; bi = j; }   // strict > : lowest index on ties
            }
            vals[s] = best;
            inds[s] = bi;
            row[bi] = -INFINITY;
        }
        float m = vals[0];
        float e[TOPK];
        float sum = 0.0f;
#pragma unroll
        for (int s = 0; s < TOPK; s++) { e[s] = expf(vals[s] - m); sum += e[s]; }
        float inv = 1.0f / sum;
        for (int j = 0; j < NEXP; j++) row[j] = 0.0f;
#pragma unroll
        for (int s = 0; s < TOPK; s++) {
            row[inds[s]] = e[s] * inv;
            sidx[tid * TOPK + s] = (float)inds[s];
        }
    }
    __syncthreads();

    // ---- coalesced writes ----
    for (int i = tid; i < TPB * NEXP; i += 256) {
        int t = i >> 6;
        int e = i & 63;
        probs_out[(size_t)(tok0 + t) * NEXP + e] = logits[t * LG_STRIDE + e];
    }
    if (idx_out) {
        for (int i = tid; i < TPB * TOPK; i += 256) {
            idx_out[(size_t)tok0 * TOPK + i] = sidx[i];
        }
    }
}

extern "C" void kernel_launch(void* const* d_in, const int* in_sizes, int n_in,
                              void* d_out, int out_size) {
    const float* X = (const float*)d_in[0];
    const float* W = (const float*)d_in[1];
    const float* B = (const float*)d_in[2];
    float* out = (float*)d_out;

    const long long PROBS_ELEMS = (long long)TOKENS * NEXP;   // 2097152
    const long long IDX_ELEMS   = (long long)TOKENS * TOPK;   // 262144
    float* idx_out = nullptr;
    if ((long long)out_size >= PROBS_ELEMS + IDX_ELEMS) idx_out = out + PROBS_ELEMS;

    topk_router_kernel<<<TOKENS / TPB, 256>>>(X, W, B, out, idx_out);
}

// round 7
// speedup vs baseline: 1.4888x; 1.4888x over previous
#include <cuda_runtime.h>
#include <cuda_bf16.h>
#include <math.h>

// TopkRouter: logits = X @ W^T + b ; top-8 ; masked softmax.
// X: [32768, 2048] f32, W: [64, 2048] f32, b: [64] f32
// out: probs [32768, 64] f32 then indices [32768, 8] (as f32).
//
// Numerics (FROZEN, matches XLA:CPU Eigen gebp bitwise): per output, serial
// ascending-k fp32 FMA within 320-wide K panels; master += panel at each
// boundary (k=320,640,...,1920); 128-wide remainder; bias added at the end.
//
// R7 layout changes (perf only, order-preserving):
//  - Xs token-major stride 33 (odd): conflict-free scalar reads AND stores.
//  - experts per thread: {4h..4h+3, 4h+32..4h+35} so the two W LDS.128 are
//    bank-conflict-free (contiguous 128B, banks 4h%32 distinct).

#define TOKENS 32768
#define EMBED 2048
#define NEXP 64
#define TOPK 8
#define TPB 128          // tokens per block
#define KT 32            // k tile
#define KC_TILES 10      // flush every 10 tiles => panel = 320 (Eigen cap)
#define XS_STRIDE 33     // odd => conflict-free scalar LDS/STS
#define WS_STRIDE 68     // 64 + 4 pad, 16B-aligned rows
#define LG_STRIDE 65     // logits row stride (conflict-free column scans)

static __device__ __forceinline__ unsigned long long pack2(float x) {
    unsigned long long r;
    asm("mov.b64 %0, {%1, %1};" : "=l"(r) : "f"(x));
    return r;
}
static __device__ __forceinline__ unsigned long long ffma2(unsigned long long a,
                                                           unsigned long long b,
                                                           unsigned long long c) {
    unsigned long long d;
    asm("fma.rn.f32x2 %0, %1, %2, %3;" : "=l"(d) : "l"(a), "l"(b), "l"(c));
    return d;
}
static __device__ __forceinline__ unsigned long long fadd2(unsigned long long a,
                                                           unsigned long long b) {
    unsigned long long d;
    asm("add.rn.f32x2 %0, %1, %2;" : "=l"(d) : "l"(a), "l"(b));
    return d;
}
static __device__ __forceinline__ void unpack2(unsigned long long v, float& lo, float& hi) {
    asm("mov.b64 {%0, %1}, %2;" : "=f"(lo), "=f"(hi) : "l"(v));
}

// shared layout (floats):
//   [0, 8320)   union: { Xs[128*33]=4224 | Ws at +4224 (32*68=2176) } OR logits[128*65]
//   [8320, 9344)  sidx[128*8]
//   [9344, 9408)  sbias[64]
#define SMEM_FLOATS (8320 + 1024 + 64)

__global__ __launch_bounds__(256, 2)
void topk_router_kernel(const float* __restrict__ X,
                        const float* __restrict__ W,
                        const float* __restrict__ B,
                        float* __restrict__ probs_out,
                        float* __restrict__ idx_out) {
    __shared__ float smem[SMEM_FLOATS];
    float* Xs     = smem;               // 128 x 33
    float* Ws     = smem + 4224;        // 32 x 68 (transposed: [k][e]); 16B-aligned
    float* logits = smem;               // 128 x 65 (overlaps tiles)
    float* sidx   = smem + 8320;        // 128 x 8
    float* sbias  = smem + 9344;        // 64

    const int tid  = threadIdx.x;
    const int tok0 = blockIdx.x * TPB;

    if (tid < NEXP) sbias[tid] = B[tid];

    const int g = tid >> 3;   // token group: tokens 4g..4g+3
    const int h = tid & 7;    // expert groups: 4h..4h+3 and 4h+32..4h+35

    // two-level fp32 accumulation: mst += til at every 320-k panel boundary
    unsigned long long mst[4][4];
    unsigned long long til[4][4];
#pragma unroll
    for (int i = 0; i < 4; i++)
#pragma unroll
        for (int j = 0; j < 4; j++) { mst[i][j] = 0ull; til[i][j] = 0ull; }

    for (int k0 = 0; k0 < EMBED; k0 += KT) {
        __syncthreads();
        // ---- load X tile: token-major stride 33; 4 scalar STS, conflict-free ----
#pragma unroll
        for (int r = 0; r < 4; r++) {
            int idx = tid + 256 * r;            // 0..1023
            int t = idx >> 3;
            int c = idx & 7;
            float4 v = *reinterpret_cast<const float4*>(
                X + (size_t)(tok0 + t) * EMBED + k0 + 4 * c);
            float* p = Xs + t * XS_STRIDE + 4 * c;
            p[0] = v.x; p[1] = v.y; p[2] = v.z; p[3] = v.w;
        }
        // ---- load W tile transposed: Ws[k][e] ----
#pragma unroll
        for (int r = 0; r < 2; r++) {
            int idx = tid + 256 * r;            // 0..511
            int e = idx >> 3;
            int c = idx & 7;
            float4 v = *reinterpret_cast<const float4*>(
                W + (size_t)e * EMBED + k0 + 4 * c);
            Ws[(4 * c + 0) * WS_STRIDE + e] = v.x;
            Ws[(4 * c + 1) * WS_STRIDE + e] = v.y;
            Ws[(4 * c + 2) * WS_STRIDE + e] = v.z;
            Ws[(4 * c + 3) * WS_STRIDE + e] = v.w;
        }
        __syncthreads();
        // ---- compute: serial ascending k within the panel ----
#pragma unroll
        for (int kk = 0; kk < KT; kk++) {
            const float* wrow = Ws + kk * WS_STRIDE;
            // experts 4h..4h+3 (contiguous 16B, conflict-free LDS.128)
            ulonglong2 wa = *reinterpret_cast<const ulonglong2*>(wrow + 4 * h);
            // experts 4h+32..4h+35 (contiguous 16B, +128B)
            ulonglong2 wb = *reinterpret_cast<const ulonglong2*>(wrow + 32 + 4 * h);
            unsigned long long xx0 = pack2(Xs[(4 * g + 0) * XS_STRIDE + kk]);
            unsigned long long xx1 = pack2(Xs[(4 * g + 1) * XS_STRIDE + kk]);
            unsigned long long xx2 = pack2(Xs[(4 * g + 2) * XS_STRIDE + kk]);
            unsigned long long xx3 = pack2(Xs[(4 * g + 3) * XS_STRIDE + kk]);
            til[0][0] = ffma2(xx0, wa.x, til[0][0]);
            til[0][1] = ffma2(xx0, wa.y, til[0][1]);
            til[0][2] = ffma2(xx0, wb.x, til[0][2]);
            til[0][3] = ffma2(xx0, wb.y, til[0][3]);
            til[1][0] = ffma2(xx1, wa.x, til[1][0]);
            til[1][1] = ffma2(xx1, wa.y, til[1][1]);
            til[1][2] = ffma2(xx1, wb.x, til[1][2]);
            til[1][3] = ffma2(xx1, wb.y, til[1][3]);
            til[2][0] = ffma2(xx2, wa.x, til[2][0]);
            til[2][1] = ffma2(xx2, wa.y, til[2][1]);
            til[2][2] = ffma2(xx2, wb.x, til[2][2]);
            til[2][3] = ffma2(xx2, wb.y, til[2][3]);
            til[3][0] = ffma2(xx3, wa.x, til[3][0]);
            til[3][1] = ffma2(xx3, wa.y, til[3][1]);
            til[3][2] = ffma2(xx3, wb.x, til[3][2]);
            til[3][3] = ffma2(xx3, wb.y, til[3][3]);
        }
        // ---- Eigen panel boundary: after tiles 9,19,...,59 (k=320,...,1920) ----
        {
            int t_idx = k0 >> 5;
            if ((t_idx + 1) % KC_TILES == 0) {
#pragma unroll
                for (int i = 0; i < 4; i++)
#pragma unroll
                    for (int j = 0; j < 4; j++) {
                        mst[i][j] = fadd2(mst[i][j], til[i][j]);
                        til[i][j] = 0ull;
                    }
            }
        }
    }
    // final remainder panel (k = 1920..2047, 128 wide)
#pragma unroll
    for (int i = 0; i < 4; i++)
#pragma unroll
        for (int j = 0; j < 4; j++) mst[i][j] = fadd2(mst[i][j], til[i][j]);

    __syncthreads();   // all warps done reading tiles; safe to overwrite with logits

    // ---- bias add + stash logits in smem ----
#pragma unroll
    for (int i = 0; i < 4; i++) {
        int t = 4 * g + i;
#pragma unroll
        for (int j = 0; j < 4; j++) {
            int e = (j < 2) ? (4 * h + 2 * j) : (32 + 4 * h + 2 * (j - 2));
            float lo, hi;
            unpack2(mst[i][j], lo, hi);
            logits[t * LG_STRIDE + e]     = lo + sbias[e];
            logits[t * LG_STRIDE + e + 1] = hi + sbias[e + 1];
        }
    }
    __syncthreads();

    // ---- top-8 + masked softmax, one thread per token ----
    if (tid < TPB) {
        float* row = logits + tid * LG_STRIDE;
        float vals[TOPK];
        int   inds[TOPK];
#pragma unroll
        for (int s = 0; s < TOPK; s++) {
            float best = -INFINITY;
            int bi = 0;
            for (int j = 0; j < NEXP; j++) {
                float v = row[j];
                if (v > best) { best = v; bi = j; }   // strict > : lowest index on ties
            }
            vals[s] = best;
            inds[s] = bi;
            row[bi] = -INFINITY;
        }
        float m = vals[0];
        float e[TOPK];
        float sum = 0.0f;
#pragma unroll
        for (int s = 0; s < TOPK; s++) { e[s] = expf(vals[s] - m); sum += e[s]; }
        float inv = 1.0f / sum;
        for (int j = 0; j < NEXP; j++) row[j] = 0.0f;
#pragma unroll
        for (int s = 0; s < TOPK; s++) {
            row[inds[s]] = e[s] * inv;
            sidx[tid * TOPK + s] = (float)inds[s];
        }
    }
    __syncthreads();

    // ---- coalesced writes ----
    for (int i = tid; i < TPB * NEXP; i += 256) {
        int t = i >> 6;
        int e = i & 63;
        probs_out[(size_t)(tok0 + t) * NEXP + e] = logits[t * LG_STRIDE + e];
    }
    if (idx_out) {
        for (int i = tid; i < TPB * TOPK; i += 256) {
            idx_out[(size_t)tok0 * TOPK + i] = sidx[i];
        }
    }
}

extern "C" void kernel_launch(void* const* d_in, const int* in_sizes, int n_in,
                              void* d_out, int out_size) {
    const float* X = (const float*)d_in[0];
    const float* W = (const float*)d_in[1];
    const float* B = (const float*)d_in[2];
    float* out = (float*)d_out;

    const long long PROBS_ELEMS = (long long)TOKENS * NEXP;   // 2097152
    const long long IDX_ELEMS   = (long long)TOKENS * TOPK;   // 262144
    float* idx_out = nullptr;
    if ((long long)out_size >= PROBS_ELEMS + IDX_ELEMS) idx_out = out + PROBS_ELEMS;

    topk_router_kernel<<<TOKENS / TPB, 256>>>(X, W, B, out, idx_out);
}